// round 3
// baseline (speedup 1.0000x reference)
#include <cuda_runtime.h>
#include <math.h>

// Problem constants (fixed by reference setup_inputs)
#define NB 16
#define NH 1024
#define NW 1024
#define GRID_ELEMS (NB * NH * NW)   // 16777216 floats for odo_grid
#define K_OUT 64                    // 4 * B rows in odo

// Vectorized zero-fill: out_size floats, float4 stores where possible.
__global__ void zero_fill_kernel(float* __restrict__ out, int n) {
    int n4 = n >> 2;  // number of full float4 chunks
    float4* out4 = (float4*)out;
    const float4 z = make_float4(0.f, 0.f, 0.f, 0.f);
    for (int i = blockIdx.x * blockDim.x + threadIdx.x; i < n4;
         i += gridDim.x * blockDim.x) {
        out4[i] = z;
    }
    // Tail (n not multiple of 4) handled by the first few threads.
    int tail = n & 3;
    int gtid = blockIdx.x * blockDim.x + threadIdx.x;
    if (gtid < tail) out[n4 * 4 + gtid] = 0.f;
}

// Single tiny kernel: for each batch, invert the affine map to find the
// candidate window whose nearest-neighbor source could be (iy,ix)=(500,200),
// evaluate the exact float32 forward condition, write 30.0 sparsely, and
// emit the sorted (h,w) index list (argwhere semantics: row-major order,
// -1 fill to 64 rows).
__global__ void odo_points_kernel(const float* __restrict__ rot,
                                  float* __restrict__ out, int out_size) {
    __shared__ int s_keys[K_OUT];
    __shared__ int s_count;
    int tid = threadIdx.x;
    if (tid == 0) s_count = 0;
    __syncthreads();

    // 16 batches x 49 window candidates = 784 threads
    int b = tid / 49;
    int j = tid % 49;
    if (b < NB) {
        float t00 = rot[b * 6 + 0];  // ca
        float t01 = rot[b * 6 + 1];  // -sa
        float t02 = rot[b * 6 + 2];  // tx
        float t10 = rot[b * 6 + 3];  // sa
        float t11 = rot[b * 6 + 4];  // ca
        float t12 = rot[b * 6 + 5];  // ty

        // Target continuous grid coords such that ix==200, iy==500:
        //   ix = 512*(grid_x + 1) - 0.5  =>  grid_x* = 200.5/512 - 1
        double gxs = 200.5 / 512.0 - 1.0;
        double gys = 500.5 / 512.0 - 1.0;
        double rx = gxs - (double)t02;
        double ry = gys - (double)t12;
        // [t00 t01; t10 t11] is a rotation (det=1): inverse = transpose.
        double gx0 = (double)t00 * rx + (double)t10 * ry;
        double gy0 = (double)t01 * rx + (double)t11 * ry;
        // Back to pixel coords: gx = (2w+1)/1024 - 1  =>  w = 512*(gx+1) - 0.5
        double w0 = 512.0 * (gx0 + 1.0) - 0.5;
        double h0 = 512.0 * (gy0 + 1.0) - 0.5;

        int wc = (int)floor(w0 + 0.5) + (j % 7) - 3;
        int hc = (int)floor(h0 + 0.5) + (j / 7) - 3;

        if (wc >= 0 && wc < NW && hc >= 0 && hc < NH) {
            // Exact float32 forward evaluation, same formula as reference.
            float gx = (2.0f * (float)wc + 1.0f) / 1024.0f - 1.0f;
            float gy = (2.0f * (float)hc + 1.0f) / 1024.0f - 1.0f;
            float grid_x = t00 * gx + t01 * gy + t02;
            float grid_y = t10 * gx + t11 * gy + t12;
            float ix = ((grid_x + 1.0f) * 1024.0f - 1.0f) * 0.5f;
            float iy = ((grid_y + 1.0f) * 1024.0f - 1.0f) * 0.5f;
            // jnp.round = round-half-to-even = rintf (default RN mode)
            float rxf = rintf(ix);
            float ryf = rintf(iy);
            rxf = fminf(fmaxf(rxf, 0.0f), (float)(NW - 1));
            ryf = fminf(fmaxf(ryf, 0.0f), (float)(NH - 1));
            if (rxf == 200.0f && ryf == 500.0f) {
                int key = (b * NH + hc) * NW + wc;  // row-major linear index
                out[key] = 30.0f;
                int slot = atomicAdd(&s_count, 1);
                if (slot < K_OUT) s_keys[slot] = key;
            }
        }
    }
    __syncthreads();

    // Single thread: sort <=64 keys (argwhere row-major order), emit odo tail.
    if (tid == 0 && out_size >= GRID_ELEMS + 2 * K_OUT) {
        int n = s_count;
        if (n > K_OUT) n = K_OUT;
        for (int i = 1; i < n; i++) {
            int k = s_keys[i];
            int p = i - 1;
            while (p >= 0 && s_keys[p] > k) {
                s_keys[p + 1] = s_keys[p];
                p--;
            }
            s_keys[p + 1] = k;
        }
        float* odo = out + GRID_ELEMS;
        for (int k = 0; k < K_OUT; k++) {
            if (k < n) {
                int key = s_keys[k];
                int ww = key % NW;
                int hh = (key / NW) % NH;
                odo[2 * k + 0] = (float)hh;
                odo[2 * k + 1] = (float)ww;
            } else {
                odo[2 * k + 0] = -1.0f;
                odo[2 * k + 1] = -1.0f;
            }
        }
    }
}

extern "C" void kernel_launch(void* const* d_in, const int* in_sizes, int n_in,
                              void* d_out, int out_size) {
    // Inputs per metadata order: d_in[0]=cost_map_batch (unused by the math),
    // d_in[1]=rot_mat (16x2x3 float32).
    const float* rot = (const float*)d_in[1];
    float* out = (float*)d_out;

    // Zero the entire output (odo_grid + odo tail) at HBM write bandwidth.
    // 148 SMs x 8 blocks x 256 threads, grid-stride over float4 chunks.
    zero_fill_kernel<<<148 * 8, 256, 0, 0>>>(out, out_size);

    // Sparse points + argwhere tail (stream-ordered after the fill).
    odo_points_kernel<<<1, 784, 0, 0>>>(rot, out, out_size);
}

// round 4
// speedup vs baseline: 1.0472x; 1.0472x over previous
#include <cuda_runtime.h>
#include <math.h>

// Problem constants (fixed by reference setup_inputs)
#define NB 16
#define NH 1024
#define NW 1024
#define GRID_ELEMS (NB * NH * NW)   // 16777216 floats for odo_grid
#define K_OUT 64                    // 4 * B rows in odo

// Vectorized zero-fill: out_size floats, float4 stores where possible.
__global__ void zero_fill_kernel(float* __restrict__ out, int n) {
    int n4 = n >> 2;  // number of full float4 chunks
    float4* out4 = (float4*)out;
    const float4 z = make_float4(0.f, 0.f, 0.f, 0.f);
    for (int i = blockIdx.x * blockDim.x + threadIdx.x; i < n4;
         i += gridDim.x * blockDim.x) {
        out4[i] = z;
    }
    // Tail (n not multiple of 4) handled by the first few threads.
    int tail = n & 3;
    int gtid = blockIdx.x * blockDim.x + threadIdx.x;
    if (gtid < tail) out[n4 * 4 + gtid] = 0.f;
}

// Single tiny kernel: for each batch, invert the affine map (all fp32 — the
// inverse only needs to locate the center of a +/-3 pixel window, ~1e-4 px
// fp32 error) to find candidates whose nearest-neighbor source could be
// (iy,ix)=(500,200), evaluate the EXACT float32 forward condition (same
// formula as the reference), write 30.0 sparsely, and emit the sorted (h,w)
// index list (argwhere semantics: row-major order, -1 fill to 64 rows).
__global__ void odo_points_kernel(const float* __restrict__ rot,
                                  float* __restrict__ out, int out_size) {
    __shared__ int s_keys[K_OUT];
    __shared__ int s_count;
    int tid = threadIdx.x;
    if (tid == 0) s_count = 0;
    __syncthreads();

    // 16 batches x 49 window candidates = 784 threads
    int b = tid / 49;
    int j = tid % 49;
    if (b < NB) {
        float t00 = rot[b * 6 + 0];  // ca
        float t01 = rot[b * 6 + 1];  // -sa
        float t02 = rot[b * 6 + 2];  // tx
        float t10 = rot[b * 6 + 3];  // sa
        float t11 = rot[b * 6 + 4];  // ca
        float t12 = rot[b * 6 + 5];  // ty

        // Target continuous grid coords such that ix==200, iy==500:
        //   ix = 512*(grid_x + 1) - 0.5  =>  grid_x* = 200.5/512 - 1
        const float gxs = 200.5f / 512.0f - 1.0f;
        const float gys = 500.5f / 512.0f - 1.0f;
        float rx = gxs - t02;
        float ry = gys - t12;
        // [t00 t01; t10 t11] is a rotation (det=1): inverse = transpose.
        float gx0 = t00 * rx + t10 * ry;
        float gy0 = t01 * rx + t11 * ry;
        // Back to pixel coords: gx = (2w+1)/1024 - 1  =>  w = 512*(gx+1) - 0.5
        float w0 = 512.0f * (gx0 + 1.0f) - 0.5f;
        float h0 = 512.0f * (gy0 + 1.0f) - 0.5f;

        int wc = (int)floorf(w0 + 0.5f) + (j % 7) - 3;
        int hc = (int)floorf(h0 + 0.5f) + (j / 7) - 3;

        if (wc >= 0 && wc < NW && hc >= 0 && hc < NH) {
            // Exact float32 forward evaluation, same formula as reference.
            float gx = (2.0f * (float)wc + 1.0f) / 1024.0f - 1.0f;
            float gy = (2.0f * (float)hc + 1.0f) / 1024.0f - 1.0f;
            float grid_x = t00 * gx + t01 * gy + t02;
            float grid_y = t10 * gx + t11 * gy + t12;
            float ix = ((grid_x + 1.0f) * 1024.0f - 1.0f) * 0.5f;
            float iy = ((grid_y + 1.0f) * 1024.0f - 1.0f) * 0.5f;
            // jnp.round = round-half-to-even = rintf (default RN mode)
            float rxf = rintf(ix);
            float ryf = rintf(iy);
            rxf = fminf(fmaxf(rxf, 0.0f), (float)(NW - 1));
            ryf = fminf(fmaxf(ryf, 0.0f), (float)(NH - 1));
            if (rxf == 200.0f && ryf == 500.0f) {
                int key = (b * NH + hc) * NW + wc;  // row-major linear index
                out[key] = 30.0f;
                int slot = atomicAdd(&s_count, 1);
                if (slot < K_OUT) s_keys[slot] = key;
            }
        }
    }
    __syncthreads();

    // Single thread: sort <=64 keys (argwhere row-major order), emit odo tail.
    if (tid == 0 && out_size >= GRID_ELEMS + 2 * K_OUT) {
        int n = s_count;
        if (n > K_OUT) n = K_OUT;
        for (int i = 1; i < n; i++) {
            int k = s_keys[i];
            int p = i - 1;
            while (p >= 0 && s_keys[p] > k) {
                s_keys[p + 1] = s_keys[p];
                p--;
            }
            s_keys[p + 1] = k;
        }
        float* odo = out + GRID_ELEMS;
        for (int k = 0; k < K_OUT; k++) {
            if (k < n) {
                int key = s_keys[k];
                int ww = key & (NW - 1);
                int hh = (key >> 10) & (NH - 1);
                odo[2 * k + 0] = (float)hh;
                odo[2 * k + 1] = (float)ww;
            } else {
                odo[2 * k + 0] = -1.0f;
                odo[2 * k + 1] = -1.0f;
            }
        }
    }
}

extern "C" void kernel_launch(void* const* d_in, const int* in_sizes, int n_in,
                              void* d_out, int out_size) {
    // Inputs per metadata order: d_in[0]=cost_map_batch (unused by the math),
    // d_in[1]=rot_mat (16x2x3 float32).
    const float* rot = (const float*)d_in[1];
    float* out = (float*)d_out;

    // Zero the entire output (odo_grid + odo tail) at HBM write bandwidth.
    zero_fill_kernel<<<148 * 12, 256, 0, 0>>>(out, out_size);

    // Sparse points + argwhere tail (stream-ordered after the fill).
    odo_points_kernel<<<1, 784, 0, 0>>>(rot, out, out_size);
}

// round 5
// speedup vs baseline: 1.3854x; 1.3229x over previous
#include <cuda_runtime.h>
#include <math.h>

// Problem constants (fixed by reference setup_inputs)
#define NB 16
#define NH 1024
#define NW 1024
#define GRID_ELEMS (NB * NH * NW)   // 16777216 floats for odo_grid
#define K_OUT 64                    // 4 * B rows in odo
#define SLOTS 8                     // per-batch key slots (>= max lattice pts in unit cell)

// Vectorized zero-fill: out_size floats, float4 stores where possible.
__global__ void zero_fill_kernel(float* __restrict__ out, int n) {
    int n4 = n >> 2;  // number of full float4 chunks
    float4* out4 = (float4*)out;
    const float4 z = make_float4(0.f, 0.f, 0.f, 0.f);
    for (int i = blockIdx.x * blockDim.x + threadIdx.x; i < n4;
         i += gridDim.x * blockDim.x) {
        out4[i] = z;
    }
    int tail = n & 3;
    int gtid = blockIdx.x * blockDim.x + threadIdx.x;
    if (gtid < tail) out[n4 * 4 + gtid] = 0.f;
}

// For each batch, invert the affine map (fp32 — only needs to locate the
// center of a +/-3 px window), evaluate the EXACT float32 reference forward
// formula on the 7x7 candidate window, write 30.0 sparsely, and emit the
// argwhere tail. Key = b*HW + h*W + w is monotone in b, so global sorted
// order = batches in order with each batch's <=4 keys sorted internally:
// no global sort needed.
__global__ void odo_points_kernel(const float* __restrict__ rot,
                                  float* __restrict__ out, int out_size) {
    __shared__ int s_bkeys[NB][SLOTS];
    __shared__ int s_cnt[NB];
    int tid = threadIdx.x;
    if (tid < NB) s_cnt[tid] = 0;
    __syncthreads();

    // 16 batches x 49 window candidates = 784 threads
    int b = tid / 49;
    int j = tid % 49;
    if (b < NB) {
        float t00 = rot[b * 6 + 0];  // ca
        float t01 = rot[b * 6 + 1];  // -sa
        float t02 = rot[b * 6 + 2];  // tx
        float t10 = rot[b * 6 + 3];  // sa
        float t11 = rot[b * 6 + 4];  // ca
        float t12 = rot[b * 6 + 5];  // ty

        // Continuous grid coords hitting (ix,iy)=(200,500):
        //   ix = 512*(grid_x + 1) - 0.5  =>  grid_x* = 200.5/512 - 1
        const float gxs = 200.5f / 512.0f - 1.0f;
        const float gys = 500.5f / 512.0f - 1.0f;
        float rx = gxs - t02;
        float ry = gys - t12;
        // Rotation (det=1): inverse = transpose.
        float gx0 = t00 * rx + t10 * ry;
        float gy0 = t01 * rx + t11 * ry;
        float w0 = 512.0f * (gx0 + 1.0f) - 0.5f;
        float h0 = 512.0f * (gy0 + 1.0f) - 0.5f;

        int wc = (int)floorf(w0 + 0.5f) + (j % 7) - 3;
        int hc = (int)floorf(h0 + 0.5f) + (j / 7) - 3;

        if (wc >= 0 && wc < NW && hc >= 0 && hc < NH) {
            // Exact float32 forward evaluation, same formula as reference.
            float gx = (2.0f * (float)wc + 1.0f) / 1024.0f - 1.0f;
            float gy = (2.0f * (float)hc + 1.0f) / 1024.0f - 1.0f;
            float grid_x = t00 * gx + t01 * gy + t02;
            float grid_y = t10 * gx + t11 * gy + t12;
            float ix = ((grid_x + 1.0f) * 1024.0f - 1.0f) * 0.5f;
            float iy = ((grid_y + 1.0f) * 1024.0f - 1.0f) * 0.5f;
            // jnp.round = round-half-to-even = rintf (default RN mode)
            float rxf = rintf(ix);
            float ryf = rintf(iy);
            rxf = fminf(fmaxf(rxf, 0.0f), (float)(NW - 1));
            ryf = fminf(fmaxf(ryf, 0.0f), (float)(NH - 1));
            if (rxf == 200.0f && ryf == 500.0f) {
                int key = (b * NH + hc) * NW + wc;  // row-major linear index
                out[key] = 30.0f;
                int slot = atomicAdd(&s_cnt[b], 1);
                if (slot < SLOTS) s_bkeys[b][slot] = key;
            }
        }
    }
    __syncthreads();

    bool tail_ok = (out_size >= GRID_ELEMS + 2 * K_OUT);
    float* odo = out + GRID_ELEMS;

    // Parallel -1 fill of the odo tail (128 floats).
    if (tail_ok && tid < 2 * K_OUT) odo[tid] = -1.0f;
    __syncthreads();

    // One thread per batch: exclusive offset, register insertion-sort of
    // <=SLOTS keys, write (h,w) pairs.
    if (tail_ok && tid < NB) {
        int off = 0;
        #pragma unroll
        for (int i = 0; i < NB; i++) {
            int c = s_cnt[i];
            if (c > SLOTS) c = SLOTS;
            if (i < tid) off += c;
        }
        int n = s_cnt[tid];
        if (n > SLOTS) n = SLOTS;
        int keys[SLOTS];
        #pragma unroll
        for (int i = 0; i < SLOTS; i++)
            keys[i] = (i < n) ? s_bkeys[tid][i] : 0x7FFFFFFF;
        // Register insertion sort (small n).
        #pragma unroll
        for (int i = 1; i < SLOTS; i++) {
            int k = keys[i];
            int p = i - 1;
            #pragma unroll
            for (int q = SLOTS - 2; q >= 0; q--) {
                if (q == p && p >= 0 && keys[p] > k) {
                    keys[p + 1] = keys[p];
                    p--;
                }
            }
            keys[p + 1] = k;
        }
        for (int i = 0; i < n; i++) {
            int pos = off + i;
            if (pos < K_OUT) {
                int key = keys[i];
                int ww = key & (NW - 1);
                int hh = (key >> 10) & (NH - 1);
                odo[2 * pos + 0] = (float)hh;
                odo[2 * pos + 1] = (float)ww;
            }
        }
    }
}

extern "C" void kernel_launch(void* const* d_in, const int* in_sizes, int n_in,
                              void* d_out, int out_size) {
    // Inputs per metadata order: d_in[0]=cost_map_batch (unused by the math),
    // d_in[1]=rot_mat (16x2x3 float32).
    const float* rot = (const float*)d_in[1];
    float* out = (float*)d_out;

    // Zero the entire output (odo_grid + odo tail) at HBM write bandwidth.
    zero_fill_kernel<<<148 * 12, 256, 0, 0>>>(out, out_size);

    // Sparse points + argwhere tail (stream-ordered after the fill).
    odo_points_kernel<<<1, 784, 0, 0>>>(rot, out, out_size);
}